// round 10
// baseline (speedup 1.0000x reference)
#include <cuda_runtime.h>
#include <cuda_bf16.h>
#include <cstdint>

#define NVSEG 29000
#define HWSZ  (1024 * 1024)
#define BATCH 16
#define BHW   (BATCH * HWSZ)

// ---------------- PTX helpers (mirrors known-good example patterns) --------
#define MBAR_INIT(a, c) \
    asm volatile("mbarrier.init.shared.b64 [%0], %1;" :: "r"(a), "r"(c) : "memory")
#define MBAR_EXPECT_TX(a, bytes) \
    asm volatile("mbarrier.arrive.expect_tx.shared.b64 _, [%0], %1;" \
                 :: "r"(a), "r"(bytes) : "memory")
#define MBAR_WAIT_PARITY(a, ph) do {                                          \
    uint32_t _m = (a); uint32_t _p = (ph); uint32_t _done;                    \
    asm volatile("{\n\t.reg .pred p;\n\t"                                     \
        "mbarrier.try_wait.parity.shared.b64 p, [%1], %2;\n\t"                \
        "selp.b32 %0, 1, 0, p;\n\t}"                                          \
        : "=r"(_done) : "r"(_m), "r"(_p) : "memory");                         \
    while (!_done) {                                                          \
        asm volatile("{\n\t.reg .pred p;\n\t"                                 \
            "mbarrier.try_wait.parity.shared.b64 p, [%1], %2, 0x989680;\n\t"  \
            "selp.b32 %0, 1, 0, p;\n\t}"                                      \
            : "=r"(_done) : "r"(_m), "r"(_p) : "memory");                     \
    }                                                                         \
} while (0)
#define BULK_G2S(dst, src, bytes, mbar) \
    asm volatile("cp.async.bulk.shared::cluster.global.mbarrier::complete_tx::bytes " \
                 "[%0], [%1], %2, [%3];" \
                 :: "r"(dst), "l"(src), "r"(bytes), "r"(mbar) : "memory")
#define BULK_S2G(gdst, ssrc, bytes) \
    asm volatile("cp.async.bulk.global.shared::cta.bulk_group [%0], [%1], %2;" \
                 :: "l"(gdst), "r"(ssrc), "r"(bytes) : "memory")
#define BULK_COMMIT()  asm volatile("cp.async.bulk.commit_group;" ::: "memory")
#define BULK_WAIT0()   asm volatile("cp.async.bulk.wait_group 0;" ::: "memory")
#define FENCE_ASYNC()  asm volatile("fence.proxy.async.shared::cta;" ::: "memory")

// __device__ globals are zero-initialized at module load.
// g_acc invariant: zero at kernel_launch entry — replaced_kernel re-zeroes.
__device__ float4 g_acc[NVSEG];
__device__ float4 g_rep[NVSEG];

// ---------------- Pass 1: TMA-staged accumulate ----------------------------
// Tile = 512 px, 256 threads, 2 px/thread. seg+img arrive via cp.async.bulk
// (TMA pipe); L1tex handles only the scattered float4 REDs.
#define ACC_TILE 512
__global__ __launch_bounds__(256) void accumulate_kernel(
    const float* __restrict__ img, const int* __restrict__ seg)
{
    __shared__ alignas(16) int   s_seg[ACC_TILE];          // 2 KB
    __shared__ alignas(16) float s_img[3 * ACC_TILE];      // 6 KB
    __shared__ alignas(8)  unsigned long long s_mbar;

    const int tid = threadIdx.x;
    const uint32_t mbar = (uint32_t)__cvta_generic_to_shared(&s_mbar);
    const uint32_t sseg = (uint32_t)__cvta_generic_to_shared(s_seg);
    const uint32_t simg = (uint32_t)__cvta_generic_to_shared(s_img);

    const long P0  = (long)blockIdx.x * ACC_TILE;
    const int  b   = (int)(P0 >> 20);
    const long rem = P0 & (HWSZ - 1);
    const float* gimg = img + (long)b * 3 * HWSZ + rem;

    if (tid == 0) MBAR_INIT(mbar, 1);
    __syncthreads();
    if (tid == 0) {
        MBAR_EXPECT_TX(mbar, (ACC_TILE * 4) * 4);   // seg + 3 channels
        BULK_G2S(sseg,            seg + P0,          ACC_TILE * 4, mbar);
        BULK_G2S(simg,            gimg + 0 * HWSZ,   ACC_TILE * 4, mbar);
        BULK_G2S(simg + ACC_TILE * 4,     gimg + 1 * HWSZ, ACC_TILE * 4, mbar);
        BULK_G2S(simg + 2 * ACC_TILE * 4, gimg + 2 * HWSZ, ACC_TILE * 4, mbar);
    }
    MBAR_WAIT_PARITY(mbar, 0);

    const int2   s  = ((const int2*)s_seg)[tid];
    const float2 c0 = ((const float2*)(s_img + 0 * ACC_TILE))[tid];
    const float2 c1 = ((const float2*)(s_img + 1 * ACC_TILE))[tid];
    const float2 c2 = ((const float2*)(s_img + 2 * ACC_TILE))[tid];

    atomicAdd(&g_acc[s.x], make_float4(c0.x, c1.x, c2.x, 1.0f));
    atomicAdd(&g_acc[s.y], make_float4(c0.y, c1.y, c2.y, 1.0f));
}

// ---------------- Pass 2: rep = fV - mean; re-zero g_acc --------------------
__global__ __launch_bounds__(512) void replaced_kernel(const float* __restrict__ fV) {
    int v = blockIdx.x * blockDim.x + threadIdx.x;
    if (v >= NVSEG) return;
    float4 a = g_acc[v];
    g_acc[v] = make_float4(0.f, 0.f, 0.f, 0.f);
    float inv = 1.0f / fmaxf(a.w, 1.0f);
    float4 r;
    r.x = fV[3 * v + 0] - a.x * inv;
    r.y = fV[3 * v + 1] - a.y * inv;
    r.z = fV[3 * v + 2] - a.z * inv;
    r.w = 0.f;
    g_rep[v] = r;
}

// ---------------- Pass 3: TMA-staged output ---------------------------------
// Tile = 1024 px, 256 threads, 4 px/thread. seg+img in via bulk load, out via
// bulk store; L1tex handles only the scattered g_rep gathers.
#define OUT_TILE 1024
__global__ __launch_bounds__(256) void output_kernel(
    const float* __restrict__ img, const int* __restrict__ seg,
    float* __restrict__ out)
{
    __shared__ alignas(16) int   s_seg[OUT_TILE];          // 4 KB
    __shared__ alignas(16) float s_img[3 * OUT_TILE];      // 12 KB
    __shared__ alignas(16) float s_out[3 * OUT_TILE];      // 12 KB
    __shared__ alignas(8)  unsigned long long s_mbar;

    const int tid = threadIdx.x;
    const uint32_t mbar = (uint32_t)__cvta_generic_to_shared(&s_mbar);
    const uint32_t sseg = (uint32_t)__cvta_generic_to_shared(s_seg);
    const uint32_t simg = (uint32_t)__cvta_generic_to_shared(s_img);
    const uint32_t sout = (uint32_t)__cvta_generic_to_shared(s_out);

    const long P0  = (long)blockIdx.x * OUT_TILE;
    const int  b   = (int)(P0 >> 20);
    const long rem = P0 & (HWSZ - 1);
    const float* gimg = img + (long)b * 3 * HWSZ + rem;

    if (tid == 0) MBAR_INIT(mbar, 1);
    __syncthreads();
    if (tid == 0) {
        MBAR_EXPECT_TX(mbar, (OUT_TILE * 4) * 4);
        BULK_G2S(sseg,            seg + P0,          OUT_TILE * 4, mbar);
        BULK_G2S(simg,            gimg + 0 * HWSZ,   OUT_TILE * 4, mbar);
        BULK_G2S(simg + OUT_TILE * 4,     gimg + 1 * HWSZ, OUT_TILE * 4, mbar);
        BULK_G2S(simg + 2 * OUT_TILE * 4, gimg + 2 * HWSZ, OUT_TILE * 4, mbar);
    }
    MBAR_WAIT_PARITY(mbar, 0);

    const int4 s = ((const int4*)s_seg)[tid];

    const float4 r0 = g_rep[s.x];
    const float4 r1 = g_rep[s.y];
    const float4 r2 = g_rep[s.z];
    const float4 r3 = g_rep[s.w];

    const float4 c0 = ((const float4*)(s_img + 0 * OUT_TILE))[tid];
    const float4 c1 = ((const float4*)(s_img + 1 * OUT_TILE))[tid];
    const float4 c2 = ((const float4*)(s_img + 2 * OUT_TILE))[tid];

    float4 o0, o1, o2;
    o0.x = c0.x + r0.x;  o0.y = c1.x + r0.y;  o0.z = c2.x + r0.z;  o0.w = c0.y + r1.x;
    o1.x = c1.y + r1.y;  o1.y = c2.y + r1.z;  o1.z = c0.z + r2.x;  o1.w = c1.z + r2.y;
    o2.x = c2.z + r2.z;  o2.y = c0.w + r3.x;  o2.z = c1.w + r3.y;  o2.w = c2.w + r3.z;

    float4* sdst = (float4*)s_out + 3 * tid;
    sdst[0] = o0;  sdst[1] = o1;  sdst[2] = o2;

    __syncthreads();
    if (tid == 0) {
        FENCE_ASYNC();
        BULK_S2G(out + P0 * 3, sout, OUT_TILE * 3 * 4);
        BULK_COMMIT();
        BULK_WAIT0();   // smem must stay valid until the bulk store drains
    }
}

extern "C" void kernel_launch(void* const* d_in, const int* in_sizes, int n_in,
                              void* d_out, int out_size)
{
    const float* img = (const float*)d_in[0];
    const int*   seg = (const int*)d_in[1];
    const float* fV  = (const float*)d_in[2];
    float* out = (float*)d_out;

    const int nvBlocks  = (NVSEG + 511) / 512;
    const int accBlocks = BHW / ACC_TILE;   // 32768
    const int outBlocks = BHW / OUT_TILE;   // 16384

    accumulate_kernel<<<accBlocks, 256>>>(img, seg);
    replaced_kernel<<<nvBlocks, 512>>>(fV);
    output_kernel<<<outBlocks, 256>>>(img, seg, out);
}

// round 11
// speedup vs baseline: 1.0184x; 1.0184x over previous
#include <cuda_runtime.h>
#include <cuda_bf16.h>

#define NVSEG 29000
#define HWSZ  (1024 * 1024)
#define BATCH 16
#define BHW   (BATCH * HWSZ)

// __device__ globals are zero-initialized at module load.
// g_acc[v] = {sum_c0, sum_c1, sum_c2, count}. Invariant: zero at
// kernel_launch entry — replaced_kernel re-zeroes after consuming.
__device__ float4 g_acc[NVSEG];
__device__ float4 g_rep[NVSEG];

// Pass 1 (proven R8 form — at its LTS-atomic floor): 2 px/thread,
// one float4 RED per pixel.
__global__ __launch_bounds__(256) void accumulate_kernel(
    const float* __restrict__ img, const int* __restrict__ seg)
{
    const long t = (long)blockIdx.x * blockDim.x + threadIdx.x;  // 0 .. BHW/2
    const long p = t << 1;
    const int  b = (int)(t >> 19);          // p >> 20
    const long rem = p & (HWSZ - 1);
    const float* base = img + (long)b * 3 * HWSZ + rem;

    const int2   s  = *(const int2*)(seg + p);
    const float2 c0 = *(const float2*)(base + 0 * HWSZ);
    const float2 c1 = *(const float2*)(base + 1 * HWSZ);
    const float2 c2 = *(const float2*)(base + 2 * HWSZ);

    atomicAdd(&g_acc[s.x], make_float4(c0.x, c1.x, c2.x, 1.0f));
    atomicAdd(&g_acc[s.y], make_float4(c0.y, c1.y, c2.y, 1.0f));
}

// Pass 2: rep[v] = fV[v] - sums[v]/max(cnt,1); reset g_acc[v] = 0.
__global__ __launch_bounds__(512) void replaced_kernel(const float* __restrict__ fV) {
    int v = blockIdx.x * blockDim.x + threadIdx.x;
    if (v >= NVSEG) return;
    float4 a = g_acc[v];
    g_acc[v] = make_float4(0.f, 0.f, 0.f, 0.f);
    float inv = 1.0f / fmaxf(a.w, 1.0f);
    float4 r;
    r.x = fV[3 * v + 0] - a.x * inv;
    r.y = fV[3 * v + 1] - a.y * inv;
    r.z = fV[3 * v + 2] - a.z * inv;
    r.w = 0.f;
    g_rep[v] = r;
}

// Pass 3 (R3 structure, single new variable: streaming cache policy on all
// single-use traffic). img/seg loads and out stores are .cs (evict-first) so
// L1 stays dedicated to the 464 KB g_rep table -> ~40-50% gather hit rate at
// 39 cyc instead of ~250 cyc L2 round trips. Gathers keep default caching.
__global__ __launch_bounds__(256) void output_kernel(
    const float* __restrict__ img, const int* __restrict__ seg,
    float* __restrict__ out)
{
    const long t = (long)blockIdx.x * blockDim.x + threadIdx.x;
    const long p = t << 2;
    const int  b = (int)(t >> 18);
    const long rem = p & (HWSZ - 1);
    const float* base = img + (long)b * 3 * HWSZ + rem;

    const int4 s = __ldcs((const int4*)(seg + p));

    const float4 r0 = g_rep[s.x];
    const float4 r1 = g_rep[s.y];
    const float4 r2 = g_rep[s.z];
    const float4 r3 = g_rep[s.w];

    const float4 c0 = __ldcs((const float4*)(base + 0 * HWSZ));
    const float4 c1 = __ldcs((const float4*)(base + 1 * HWSZ));
    const float4 c2 = __ldcs((const float4*)(base + 2 * HWSZ));

    float4 o0, o1, o2;
    o0.x = c0.x + r0.x;  o0.y = c1.x + r0.y;  o0.z = c2.x + r0.z;  o0.w = c0.y + r1.x;
    o1.x = c1.y + r1.y;  o1.y = c2.y + r1.z;  o1.z = c0.z + r2.x;  o1.w = c1.z + r2.y;
    o2.x = c2.z + r2.z;  o2.y = c0.w + r3.x;  o2.z = c1.w + r3.y;  o2.w = c2.w + r3.z;

    float4* dst = (float4*)(out + p * 3);   // 12t floats -> 16B aligned
    __stcs(dst + 0, o0);
    __stcs(dst + 1, o1);
    __stcs(dst + 2, o2);
}

extern "C" void kernel_launch(void* const* d_in, const int* in_sizes, int n_in,
                              void* d_out, int out_size)
{
    const float* img = (const float*)d_in[0];
    const int*   seg = (const int*)d_in[1];
    const float* fV  = (const float*)d_in[2];
    float* out = (float*)d_out;

    const int nvBlocks  = (NVSEG + 511) / 512;
    const int accBlocks = (BHW / 2) / 256;   // 32768
    const int outBlocks = (BHW / 4) / 256;   // 16384

    accumulate_kernel<<<accBlocks, 256>>>(img, seg);
    replaced_kernel<<<nvBlocks, 512>>>(fV);
    output_kernel<<<outBlocks, 256>>>(img, seg, out);
}